// round 15
// baseline (speedup 1.0000x reference)
#include <cuda_runtime.h>
#include <cuda_fp16.h>

#define TT   1000
#define NCH  4096

// scratch (no cudaMalloc allowed)
__device__ float g_seq[NCH * TT];     // LSTM input, [chain][t], 16 MB
__device__ float g_feat[NCH * 32];    // [chain][ h_fwd(16) | h_bwd(16) ]

__device__ __forceinline__ float ex2f(float x) {
    float r; asm("ex2.approx.f32 %0, %1;" : "=f"(r) : "f"(x)); return r;
}
__device__ __forceinline__ float rcpf(float x) {
    float r; asm("rcp.approx.f32 %0, %1;" : "=f"(r) : "f"(x)); return r;
}

// FMA-pipe exp2, two-sided clamp |x|<=60: rint magic + degree-6 Taylor.
// rel err ~1.2e-7 (validated R6).
__device__ __forceinline__ float exp2_poly(float x) {
    x = fminf(fmaxf(x, -60.0f), 60.0f);
    const float MAGIC = 12582912.0f;              // 1.5 * 2^23
    const float tbig  = x + MAGIC;
    const float fi    = tbig - MAGIC;             // rint(x)
    const float f     = x - fi;
    const int   ii    = __float_as_int(tbig) - __float_as_int(MAGIC);
    const float sc    = __int_as_float((ii + 127) << 23);
    const float u     = f * 0.6931471805599453f;
    float p = fmaf(u, 1.3888889e-3f, 8.3333333e-3f);
    p = fmaf(p, u, 4.1666667e-2f);
    p = fmaf(p, u, 1.6666667e-1f);
    p = fmaf(p, u, 0.5f);
    p = fmaf(p, u, 1.0f);
    p = fmaf(p, u, 1.0f);
    return p * sc;
}

__device__ __forceinline__ unsigned pack_h2(float a, float b) {
    __half2 v = __halves2half2(__float2half_rn(a), __float2half_rn(b));
    return *(unsigned*)&v;
}

__device__ __forceinline__ void mma16816(float d[4], const unsigned a[4], const unsigned b[2]) {
    asm volatile("mma.sync.aligned.m16n8k16.row.col.f32.f16.f16.f32 "
                 "{%0,%1,%2,%3}, {%4,%5,%6,%7}, {%8,%9}, {%0,%1,%2,%3};"
                 : "+f"(d[0]), "+f"(d[1]), "+f"(d[2]), "+f"(d[3])
                 : "r"(a[0]), "r"(a[1]), "r"(a[2]), "r"(a[3]),
                   "r"(b[0]), "r"(b[1]));
}

__device__ __forceinline__ float gelu_exact(float v) {
    return 0.5f * v * (1.0f + erff(v * 0.70710678118654752f));
}

// ---------------------------------------------------------------------------
// 4-state LSTM activation, 21 MUFU/warp-step:
//   per state: 3 ex2 (i,f,o) + FMA-poly exp2 (g) + 1 gate-rcp + 1 ex2 (c)
//   plus ONE batched rcp for the four tanh(c) denominators.
// Gate section identical in structure to R13 (shortest measured path).
// tanh(c) uses e=2^(-2|c|log2e) in (0,1] -> dc in (1,2], batch-safe;
// sign restored by copysign.
// ---------------------------------------------------------------------------
__device__ __forceinline__ void lstm_act4(const float gi[4], const float gf[4],
                                          const float gg[4], const float go[4],
                                          float c[4], float h[4]) {
    const float NL2E  = -1.4426950408889634f;
    const float N2L2E = -2.8853900817779268f;
    float so[4], ec[4], dc[4];
#pragma unroll
    for (int q = 0; q < 4; q++) {
        const float ei = ex2f(gi[q] * NL2E);            // MUFU
        const float ef = ex2f(gf[q] * NL2E);            // MUFU
        const float eo = ex2f(go[q] * NL2E);            // MUFU
        const float eg = exp2_poly(gg[q] * N2L2E);      // FMA pipe
        const float di = 1.0f + ei, df = 1.0f + ef, dg = 1.0f + eg, dd = 1.0f + eo;
        const float p1 = di * df;
        const float p2 = p1 * dg;
        const float p3 = p2 * dd;
        const float r  = rcpf(p3);                      // MUFU (1 per 4 gates)
        so[q]          = r  * p2;                       // sigmoid(go)
        const float r2 = r  * dd;
        const float tg = fmaf(2.0f, r2 * p1, -1.0f);    // tanh(gg)
        const float r3 = r2 * dg;
        const float sf = r3 * di;                       // sigmoid(gf)
        const float si = r3 * df;                       // sigmoid(gi)
        c[q] = fmaf(sf, c[q], si * tg);
        ec[q] = ex2f(fabsf(c[q]) * N2L2E);              // MUFU, in (0,1]
        dc[q] = 1.0f + ec[q];                           // in (1,2]
    }
    // ONE batched rcp for all four tanh(c) denominators (products <= 16)
    const float q01 = dc[0] * dc[1];
    const float q23 = dc[2] * dc[3];
    const float rq  = rcpf(q01 * q23);                  // MUFU
    const float rA  = rq * q23;                         // 1/q01
    const float rB  = rq * q01;                         // 1/q23
    h[0] = so[0] * copysignf((1.0f - ec[0]) * (rA * dc[1]), c[0]);
    h[1] = so[1] * copysignf((1.0f - ec[1]) * (rA * dc[0]), c[1]);
    h[2] = so[2] * copysignf((1.0f - ec[2]) * (rB * dc[3]), c[2]);
    h[3] = so[3] * copysignf((1.0f - ec[3]) * (rB * dc[2]), c[3]);
}

// ---------------------------------------------------------------------------
// Kernel 1: fused depthwise-conv(5,pad2)+BN+GELU x2. One block per (b,c) row.
// ---------------------------------------------------------------------------
__global__ void __launch_bounds__(256) prep_kernel(
    const float* __restrict__ x,
    const float* __restrict__ c1w, const float* __restrict__ c1b,
    const float* __restrict__ b1g, const float* __restrict__ b1b,
    const float* __restrict__ b1m, const float* __restrict__ b1v,
    const float* __restrict__ c2w, const float* __restrict__ c2b,
    const float* __restrict__ b2g, const float* __restrict__ b2b,
    const float* __restrict__ b2m, const float* __restrict__ b2v)
{
    __shared__ float xs[TT + 4];
    __shared__ float ys[TT + 4];

    const int chain = blockIdx.x;
    const int ch    = chain & 63;
    const int tid   = threadIdx.x;

    if (tid < 2) {
        xs[tid] = 0.0f; xs[TT + 2 + tid] = 0.0f;
        ys[tid] = 0.0f; ys[TT + 2 + tid] = 0.0f;
    }
    const float* xr = x + (size_t)chain * TT;
    for (int t = tid; t < TT; t += 256) xs[t + 2] = xr[t];

    const float w0 = c1w[ch * 5 + 0], w1 = c1w[ch * 5 + 1], w2 = c1w[ch * 5 + 2],
                w3 = c1w[ch * 5 + 3], w4 = c1w[ch * 5 + 4];
    const float s1 = b1g[ch] * rsqrtf(b1v[ch] + 1e-5f);
    const float d1 = (c1b[ch] - b1m[ch]) * s1 + b1b[ch];

    __syncthreads();
    for (int t = tid; t < TT; t += 256) {
        float a = xs[t] * w0;
        a = fmaf(xs[t + 1], w1, a);
        a = fmaf(xs[t + 2], w2, a);
        a = fmaf(xs[t + 3], w3, a);
        a = fmaf(xs[t + 4], w4, a);
        ys[t + 2] = gelu_exact(fmaf(a, s1, d1));
    }

    const float u0 = c2w[ch * 5 + 0], u1 = c2w[ch * 5 + 1], u2 = c2w[ch * 5 + 2],
                u3 = c2w[ch * 5 + 3], u4 = c2w[ch * 5 + 4];
    const float s2 = b2g[ch] * rsqrtf(b2v[ch] + 1e-5f);
    const float d2 = (c2b[ch] - b2m[ch]) * s2 + b2b[ch];

    __syncthreads();
    float* outr = g_seq + (size_t)chain * TT;
    for (int t = tid; t < TT; t += 256) {
        float a = ys[t] * u0;
        a = fmaf(ys[t + 1], u1, a);
        a = fmaf(ys[t + 2], u2, a);
        a = fmaf(ys[t + 3], u3, a);
        a = fmaf(ys[t + 4], u4, a);
        outr[t] = gelu_exact(fmaf(a, s2, d2));
    }
}

// ---------------------------------------------------------------------------
// Kernel 2: LSTM via HMMA, 8 same-direction chains per warp (full N=8).
// R14 = R13 structure (plain-f16 h, 4 HMMA/step, smem h-exchange, one
// syncwarp/step) + 21-MUFU activation (poly g-gate, batched tanh-c rcp).
// Lane (g,t): D rows g,g+8 / cols 2t,2t+1 hold ALL FOUR gates for its
// 4 states (units g,g+8 x chains 2t,2t+1); activation in place.
// ---------------------------------------------------------------------------
__global__ void __launch_bounds__(128) lstm_kernel(
    const float* __restrict__ wihf, const float* __restrict__ whhf,
    const float* __restrict__ bihf, const float* __restrict__ bhhf,
    const float* __restrict__ wihr, const float* __restrict__ whhr,
    const float* __restrict__ bihr, const float* __restrict__ bhhr)
{
    // per-warp h buffer, f16x2 (chains 2p|2p+1): [2 parity][4 pairs][16 units]
    __shared__ __align__(16) unsigned hbuf_s[4][2][4][16];

    const int tid  = threadIdx.x;
    const int wid  = tid >> 5;
    const int lane = tid & 31;
    const int wg   = blockIdx.x * 4 + wid;          // 0..1023
    const bool bwd = (wg >= 512);
    const int cb   = 8 * (bwd ? wg - 512 : wg);     // chain base (8 chains)

    const float* wih = bwd ? wihr : wihf;
    const float* whh = bwd ? whhr : whhf;
    const float* bih = bwd ? bihr : bihf;
    const float* bhh = bwd ? bhhr : bhhf;

    unsigned* hbW = &hbuf_s[wid][0][0][0];
    for (int i = lane; i < 2 * 4 * 16; i += 32) hbW[i] = 0u;

    const int g = lane >> 2;      // MMA group: D rows g, g+8; B col(chain) g
    const int t = lane & 3;       // MMA thread-in-group: D cols 2t, 2t+1

    // ---- A fragments (f16 W_hh), bias and w_ih per gate tile ----
    unsigned Ahi[4][4];
    float bb0[4], bb1[4], wi0[4], wi1[4];
#pragma unroll
    for (int m = 0; m < 4; m++) {
        const int r0 = m * 16 + g;
        const int r1 = r0 + 8;
        const float* W0 = whh + r0 * 16;
        const float* W1 = whh + r1 * 16;
        Ahi[m][0] = pack_h2(W0[2*t],   W0[2*t+1]);
        Ahi[m][1] = pack_h2(W1[2*t],   W1[2*t+1]);
        Ahi[m][2] = pack_h2(W0[2*t+8], W0[2*t+9]);
        Ahi[m][3] = pack_h2(W1[2*t+8], W1[2*t+9]);
        bb0[m] = bih[r0] + bhh[r0];
        bb1[m] = bih[r1] + bhh[r1];
        wi0[m] = wih[r0];
        wi1[m] = wih[r1];
    }

    // x staging: lane = 4*chain + substep; coalesced 16B runs per chain
    const int xc  = lane >> 2;          // chain 0..7
    const int xs_ = lane & 3;           // substep 0..3
    const float* seqc = g_seq + (size_t)(cb + xc) * TT;

    // B-build addressing: need chain g -> pair g>>1, slot g&1
    const int bpair = g >> 1;
    const unsigned psel = (g & 1) ? 0x7632u : 0x5410u;

    // states owned by this lane: q=0 ->(g,2t)  q=1 ->(g,2t+1)
    //                            q=2 ->(g+8,2t) q=3 ->(g+8,2t+1)
    float c4[4]   = {0.0f, 0.0f, 0.0f, 0.0f};
    float hout[4] = {0.0f, 0.0f, 0.0f, 0.0f};

    int par = 0;
    for (int r = 0; r < 250; r++) {
        const int tt = r * 4 + xs_;
        const float xv = seqc[bwd ? (TT - 1 - tt) : tt];

#pragma unroll
        for (int s = 0; s < 4; s++) {
            __syncwarp();      // prev step's h writes -> visible for B-build

            // broadcast x of chains 2t, 2t+1 for this step
            const float xA = __shfl_sync(0xffffffffu, xv, 8 * t + s);
            const float xB = __shfl_sync(0xffffffffu, xv, 8 * t + 4 + s);

            // B fragment: h(t-1) units {2t,2t+1} and {2t+8,2t+9}, chain g
            const unsigned* hbp = hbW + par * 64 + bpair * 16;
            const uint2 u01 = *(const uint2*)(hbp + 2 * t);       // units 2t,2t+1
            const uint2 u89 = *(const uint2*)(hbp + 2 * t + 8);   // units 2t+8,2t+9
            unsigned B[2];
            B[0] = __byte_perm(u01.x, u01.y, psel);
            B[1] = __byte_perm(u89.x, u89.y, psel);

            // D init: bias + w_ih * x  (rows g, g+8; cols 2t, 2t+1)
            float d[4][4];
#pragma unroll
            for (int m = 0; m < 4; m++) {
                d[m][0] = fmaf(wi0[m], xA, bb0[m]);
                d[m][1] = fmaf(wi0[m], xB, bb0[m]);
                d[m][2] = fmaf(wi1[m], xA, bb1[m]);
                d[m][3] = fmaf(wi1[m], xB, bb1[m]);
            }

            // 4 HMMA: W_f16 * h_f16 (fp32 accumulate)
#pragma unroll
            for (int m = 0; m < 4; m++)
                mma16816(d[m], Ahi[m], B);

            // activate in place (d[m][q] = gate m of state q)
            lstm_act4(d[0], d[1], d[2], d[3], c4, hout);

            // publish h for next step's B-build
            unsigned* ho = hbW + (par ^ 1) * 64 + t * 16;
            ho[g]     = pack_h2(hout[0], hout[1]);
            ho[g + 8] = pack_h2(hout[2], hout[3]);

            par ^= 1;
        }
    }

    // final h: lane owns (unit g, chains cb+2t, cb+2t+1) and (unit g+8, same)
    const int off = bwd ? 16 : 0;
    g_feat[(cb + 2 * t)     * 32 + off + g]     = hout[0];
    g_feat[(cb + 2 * t + 1) * 32 + off + g]     = hout[1];
    g_feat[(cb + 2 * t)     * 32 + off + g + 8] = hout[2];
    g_feat[(cb + 2 * t + 1) * 32 + off + g + 8] = hout[3];
}

// ---------------------------------------------------------------------------
// Kernel 3: out[n,e] = feat[n,:] . lin_w[e,:] + lin_b[e]
// ---------------------------------------------------------------------------
__global__ void __launch_bounds__(256) linear_kernel(
    const float* __restrict__ lw, const float* __restrict__ lb,
    float* __restrict__ out)
{
    const int idx = blockIdx.x * 256 + threadIdx.x;    // 131072 total
    const int n = idx >> 5;
    const int e = idx & 31;
    const float* f = g_feat + n * 32;
    const float* wp = lw + e * 32;
    float acc = lb[e];
#pragma unroll
    for (int k = 0; k < 32; k++) acc = fmaf(f[k], wp[k], acc);
    out[idx] = acc;
}

// ---------------------------------------------------------------------------
extern "C" void kernel_launch(void* const* d_in, const int* in_sizes, int n_in,
                              void* d_out, int out_size)
{
    const float* x      = (const float*)d_in[0];
    const float* c1w    = (const float*)d_in[1];
    const float* c1b    = (const float*)d_in[2];
    const float* b1g    = (const float*)d_in[3];
    const float* b1b    = (const float*)d_in[4];
    const float* b1m    = (const float*)d_in[5];
    const float* b1v    = (const float*)d_in[6];
    const float* c2w    = (const float*)d_in[7];
    const float* c2b    = (const float*)d_in[8];
    const float* b2g    = (const float*)d_in[9];
    const float* b2b    = (const float*)d_in[10];
    const float* b2m    = (const float*)d_in[11];
    const float* b2v    = (const float*)d_in[12];
    const float* wihf   = (const float*)d_in[13];
    const float* whhf   = (const float*)d_in[14];
    const float* bihf   = (const float*)d_in[15];
    const float* bhhf   = (const float*)d_in[16];
    const float* wihr   = (const float*)d_in[17];
    const float* whhr   = (const float*)d_in[18];
    const float* bihr   = (const float*)d_in[19];
    const float* bhhr   = (const float*)d_in[20];
    const float* lw     = (const float*)d_in[21];
    const float* lb     = (const float*)d_in[22];
    float* out = (float*)d_out;

    prep_kernel<<<NCH, 256>>>(x, c1w, c1b, b1g, b1b, b1m, b1v,
                              c2w, c2b, b2g, b2b, b2m, b2v);
    lstm_kernel<<<256, 128>>>(wihf, whhf, bihf, bhhf,
                              wihr, whhr, bihr, bhhr);
    linear_kernel<<<(NCH * 32) / 256, 256>>>(lw, lb, out);
}

// round 16
// speedup vs baseline: 1.7538x; 1.7538x over previous
#include <cuda_runtime.h>
#include <cuda_fp16.h>

#define TT   1000
#define NCH  4096

// scratch (no cudaMalloc allowed)
__device__ float g_seq[NCH * TT];     // LSTM input, [chain][t], 16 MB
__device__ float g_feat[NCH * 32];    // [chain][ h_fwd(16) | h_bwd(16) ]

__device__ __forceinline__ float tanhfast(float x) {
    float r; asm("tanh.approx.f32 %0, %1;" : "=f"(r) : "f"(x)); return r;
}

// MUFU.TANH LSTM cell update: 5 MUFU + ~6 FMA per state.
// Inputs gi,gf,go are PRE-HALVED (W,b scaled by 0.5 at load):
//   sigmoid(x) = 0.5*tanh(x/2) + 0.5
__device__ __forceinline__ void lstm_act(float gih, float gfh, float gg, float goh,
                                         float& c, float& h) {
    const float si = fmaf(0.5f, tanhfast(gih), 0.5f);   // MUFU.TANH
    const float sf = fmaf(0.5f, tanhfast(gfh), 0.5f);   // MUFU.TANH
    const float so = fmaf(0.5f, tanhfast(goh), 0.5f);   // MUFU.TANH
    const float tg = tanhfast(gg);                      // MUFU.TANH
    c = fmaf(sf, c, si * tg);
    h = so * tanhfast(c);                               // MUFU.TANH
}

__device__ __forceinline__ unsigned pack_h2(float a, float b) {
    __half2 v = __halves2half2(__float2half_rn(a), __float2half_rn(b));
    return *(unsigned*)&v;
}

__device__ __forceinline__ void mma16816(float d[4], const unsigned a[4], const unsigned b[2]) {
    asm volatile("mma.sync.aligned.m16n8k16.row.col.f32.f16.f16.f32 "
                 "{%0,%1,%2,%3}, {%4,%5,%6,%7}, {%8,%9}, {%0,%1,%2,%3};"
                 : "+f"(d[0]), "+f"(d[1]), "+f"(d[2]), "+f"(d[3])
                 : "r"(a[0]), "r"(a[1]), "r"(a[2]), "r"(a[3]),
                   "r"(b[0]), "r"(b[1]));
}

__device__ __forceinline__ float gelu_exact(float v) {
    return 0.5f * v * (1.0f + erff(v * 0.70710678118654752f));
}

// ---------------------------------------------------------------------------
// Kernel 1: fused depthwise-conv(5,pad2)+BN+GELU x2. One block per (b,c) row.
// ---------------------------------------------------------------------------
__global__ void __launch_bounds__(256) prep_kernel(
    const float* __restrict__ x,
    const float* __restrict__ c1w, const float* __restrict__ c1b,
    const float* __restrict__ b1g, const float* __restrict__ b1b,
    const float* __restrict__ b1m, const float* __restrict__ b1v,
    const float* __restrict__ c2w, const float* __restrict__ c2b,
    const float* __restrict__ b2g, const float* __restrict__ b2b,
    const float* __restrict__ b2m, const float* __restrict__ b2v)
{
    __shared__ float xs[TT + 4];
    __shared__ float ys[TT + 4];

    const int chain = blockIdx.x;
    const int ch    = chain & 63;
    const int tid   = threadIdx.x;

    if (tid < 2) {
        xs[tid] = 0.0f; xs[TT + 2 + tid] = 0.0f;
        ys[tid] = 0.0f; ys[TT + 2 + tid] = 0.0f;
    }
    const float* xr = x + (size_t)chain * TT;
    for (int t = tid; t < TT; t += 256) xs[t + 2] = xr[t];

    const float w0 = c1w[ch * 5 + 0], w1 = c1w[ch * 5 + 1], w2 = c1w[ch * 5 + 2],
                w3 = c1w[ch * 5 + 3], w4 = c1w[ch * 5 + 4];
    const float s1 = b1g[ch] * rsqrtf(b1v[ch] + 1e-5f);
    const float d1 = (c1b[ch] - b1m[ch]) * s1 + b1b[ch];

    __syncthreads();
    for (int t = tid; t < TT; t += 256) {
        float a = xs[t] * w0;
        a = fmaf(xs[t + 1], w1, a);
        a = fmaf(xs[t + 2], w2, a);
        a = fmaf(xs[t + 3], w3, a);
        a = fmaf(xs[t + 4], w4, a);
        ys[t + 2] = gelu_exact(fmaf(a, s1, d1));
    }

    const float u0 = c2w[ch * 5 + 0], u1 = c2w[ch * 5 + 1], u2 = c2w[ch * 5 + 2],
                u3 = c2w[ch * 5 + 3], u4 = c2w[ch * 5 + 4];
    const float s2 = b2g[ch] * rsqrtf(b2v[ch] + 1e-5f);
    const float d2 = (c2b[ch] - b2m[ch]) * s2 + b2b[ch];

    __syncthreads();
    float* outr = g_seq + (size_t)chain * TT;
    for (int t = tid; t < TT; t += 256) {
        float a = ys[t] * u0;
        a = fmaf(ys[t + 1], u1, a);
        a = fmaf(ys[t + 2], u2, a);
        a = fmaf(ys[t + 3], u3, a);
        a = fmaf(ys[t + 4], u4, a);
        outr[t] = gelu_exact(fmaf(a, s2, d2));
    }
}

// ---------------------------------------------------------------------------
// Kernel 2: LSTM via HMMA, 8 same-direction chains per warp (full N=8).
// R15 = R13 structure (plain-f16 h, 4 HMMA/step, smem h-exchange, one
// syncwarp/step) + MUFU.TANH activation (5 MUFU + 6 FMA per state).
// Gates i,f,o are computed PRE-HALVED: their W_hh fragments, w_ih and
// biases are scaled by 0.5 at load so sigmoid(x)=0.5*tanh(x/2)+0.5 needs
// no runtime scaling. Gate g (m=2) unscaled.
// Lane (g,t): D rows g,g+8 / cols 2t,2t+1 hold ALL FOUR gates for its
// 4 states (units g,g+8 x chains 2t,2t+1); activation in place.
// ---------------------------------------------------------------------------
__global__ void __launch_bounds__(128) lstm_kernel(
    const float* __restrict__ wihf, const float* __restrict__ whhf,
    const float* __restrict__ bihf, const float* __restrict__ bhhf,
    const float* __restrict__ wihr, const float* __restrict__ whhr,
    const float* __restrict__ bihr, const float* __restrict__ bhhr)
{
    // per-warp h buffer, f16x2 (chains 2p|2p+1): [2 parity][4 pairs][16 units]
    __shared__ __align__(16) unsigned hbuf_s[4][2][4][16];

    const int tid  = threadIdx.x;
    const int wid  = tid >> 5;
    const int lane = tid & 31;
    const int wg   = blockIdx.x * 4 + wid;          // 0..1023
    const bool bwd = (wg >= 512);
    const int cb   = 8 * (bwd ? wg - 512 : wg);     // chain base (8 chains)

    const float* wih = bwd ? wihr : wihf;
    const float* whh = bwd ? whhr : whhf;
    const float* bih = bwd ? bihr : bihf;
    const float* bhh = bwd ? bhhr : bhhf;

    unsigned* hbW = &hbuf_s[wid][0][0][0];
    for (int i = lane; i < 2 * 4 * 16; i += 32) hbW[i] = 0u;

    const int g = lane >> 2;      // MMA group: D rows g, g+8; B col(chain) g
    const int t = lane & 3;       // MMA thread-in-group: D cols 2t, 2t+1

    // ---- A fragments (f16 W_hh), bias and w_ih per gate tile ----
    // Gates i (m=0), f (m=1), o (m=3): scaled by 0.5 (sigmoid-from-tanh).
    unsigned Ahi[4][4];
    float bb0[4], bb1[4], wi0[4], wi1[4];
#pragma unroll
    for (int m = 0; m < 4; m++) {
        const float sc = (m == 2) ? 1.0f : 0.5f;
        const int r0 = m * 16 + g;
        const int r1 = r0 + 8;
        const float* W0 = whh + r0 * 16;
        const float* W1 = whh + r1 * 16;
        Ahi[m][0] = pack_h2(sc * W0[2*t],   sc * W0[2*t+1]);
        Ahi[m][1] = pack_h2(sc * W1[2*t],   sc * W1[2*t+1]);
        Ahi[m][2] = pack_h2(sc * W0[2*t+8], sc * W0[2*t+9]);
        Ahi[m][3] = pack_h2(sc * W1[2*t+8], sc * W1[2*t+9]);
        bb0[m] = sc * (bih[r0] + bhh[r0]);
        bb1[m] = sc * (bih[r1] + bhh[r1]);
        wi0[m] = sc * wih[r0];
        wi1[m] = sc * wih[r1];
    }

    // x staging: lane = 4*chain + substep; coalesced 16B runs per chain
    const int xc  = lane >> 2;          // chain 0..7
    const int xs_ = lane & 3;           // substep 0..3
    const float* seqc = g_seq + (size_t)(cb + xc) * TT;

    // B-build addressing: need chain g -> pair g>>1, slot g&1
    const int bpair = g >> 1;
    const unsigned psel = (g & 1) ? 0x7632u : 0x5410u;

    // states owned by this lane: q=0 ->(g,2t)  q=1 ->(g,2t+1)
    //                            q=2 ->(g+8,2t) q=3 ->(g+8,2t+1)
    float c4[4]   = {0.0f, 0.0f, 0.0f, 0.0f};
    float hout[4] = {0.0f, 0.0f, 0.0f, 0.0f};

    int par = 0;
    for (int r = 0; r < 250; r++) {
        const int tt = r * 4 + xs_;
        const float xv = seqc[bwd ? (TT - 1 - tt) : tt];

#pragma unroll
        for (int s = 0; s < 4; s++) {
            __syncwarp();      // prev step's h writes -> visible for B-build

            // broadcast x of chains 2t, 2t+1 for this step
            const float xA = __shfl_sync(0xffffffffu, xv, 8 * t + s);
            const float xB = __shfl_sync(0xffffffffu, xv, 8 * t + 4 + s);

            // B fragment: h(t-1) units {2t,2t+1} and {2t+8,2t+9}, chain g
            const unsigned* hbp = hbW + par * 64 + bpair * 16;
            const uint2 u01 = *(const uint2*)(hbp + 2 * t);       // units 2t,2t+1
            const uint2 u89 = *(const uint2*)(hbp + 2 * t + 8);   // units 2t+8,2t+9
            unsigned B[2];
            B[0] = __byte_perm(u01.x, u01.y, psel);
            B[1] = __byte_perm(u89.x, u89.y, psel);

            // D init: bias + w_ih * x  (rows g, g+8; cols 2t, 2t+1)
            float d[4][4];
#pragma unroll
            for (int m = 0; m < 4; m++) {
                d[m][0] = fmaf(wi0[m], xA, bb0[m]);
                d[m][1] = fmaf(wi0[m], xB, bb0[m]);
                d[m][2] = fmaf(wi1[m], xA, bb1[m]);
                d[m][3] = fmaf(wi1[m], xB, bb1[m]);
            }

            // 4 HMMA: W_f16 * h_f16 (fp32 accumulate)
#pragma unroll
            for (int m = 0; m < 4; m++)
                mma16816(d[m], Ahi[m], B);

            // activate in place (d[m][q] = gate m of state q; i,f,o pre-halved)
#pragma unroll
            for (int q = 0; q < 4; q++)
                lstm_act(d[0][q], d[1][q], d[2][q], d[3][q], c4[q], hout[q]);

            // publish h for next step's B-build
            unsigned* ho = hbW + (par ^ 1) * 64 + t * 16;
            ho[g]     = pack_h2(hout[0], hout[1]);
            ho[g + 8] = pack_h2(hout[2], hout[3]);

            par ^= 1;
        }
    }

    // final h: lane owns (unit g, chains cb+2t, cb+2t+1) and (unit g+8, same)
    const int off = bwd ? 16 : 0;
    g_feat[(cb + 2 * t)     * 32 + off + g]     = hout[0];
    g_feat[(cb + 2 * t + 1) * 32 + off + g]     = hout[1];
    g_feat[(cb + 2 * t)     * 32 + off + g + 8] = hout[2];
    g_feat[(cb + 2 * t + 1) * 32 + off + g + 8] = hout[3];
}

// ---------------------------------------------------------------------------
// Kernel 3: out[n,e] = feat[n,:] . lin_w[e,:] + lin_b[e]
// ---------------------------------------------------------------------------
__global__ void __launch_bounds__(256) linear_kernel(
    const float* __restrict__ lw, const float* __restrict__ lb,
    float* __restrict__ out)
{
    const int idx = blockIdx.x * 256 + threadIdx.x;    // 131072 total
    const int n = idx >> 5;
    const int e = idx & 31;
    const float* f = g_feat + n * 32;
    const float* wp = lw + e * 32;
    float acc = lb[e];
#pragma unroll
    for (int k = 0; k < 32; k++) acc = fmaf(f[k], wp[k], acc);
    out[idx] = acc;
}

// ---------------------------------------------------------------------------
extern "C" void kernel_launch(void* const* d_in, const int* in_sizes, int n_in,
                              void* d_out, int out_size)
{
    const float* x      = (const float*)d_in[0];
    const float* c1w    = (const float*)d_in[1];
    const float* c1b    = (const float*)d_in[2];
    const float* b1g    = (const float*)d_in[3];
    const float* b1b    = (const float*)d_in[4];
    const float* b1m    = (const float*)d_in[5];
    const float* b1v    = (const float*)d_in[6];
    const float* c2w    = (const float*)d_in[7];
    const float* c2b    = (const float*)d_in[8];
    const float* b2g    = (const float*)d_in[9];
    const float* b2b    = (const float*)d_in[10];
    const float* b2m    = (const float*)d_in[11];
    const float* b2v    = (const float*)d_in[12];
    const float* wihf   = (const float*)d_in[13];
    const float* whhf   = (const float*)d_in[14];
    const float* bihf   = (const float*)d_in[15];
    const float* bhhf   = (const float*)d_in[16];
    const float* wihr   = (const float*)d_in[17];
    const float* whhr   = (const float*)d_in[18];
    const float* bihr   = (const float*)d_in[19];
    const float* bhhr   = (const float*)d_in[20];
    const float* lw     = (const float*)d_in[21];
    const float* lb     = (const float*)d_in[22];
    float* out = (float*)d_out;

    prep_kernel<<<NCH, 256>>>(x, c1w, c1b, b1g, b1b, b1m, b1v,
                              c2w, c2b, b2g, b2b, b2m, b2v);
    lstm_kernel<<<256, 128>>>(wihf, whhf, bihf, bhhf,
                              wihr, whhr, bihr, bhhr);
    linear_kernel<<<(NCH * 32) / 256, 256>>>(lw, lb, out);
}